// round 5
// baseline (speedup 1.0000x reference)
#include <cuda_runtime.h>
#include <math.h>

// Problem constants (fixed by the benchmark)
#define LSEQ 1024
#define NBH  32          // B*H = 4*8
#define TI   8           // i-rows per CTA
#define TJ   8           // j per tile
#define NT   (LSEQ/TJ)   // 128 tiles
#define NTHREADS 256
#define NBLOCKS (LSEQ/TI) // 128

#define QS_STRIDE 36             // padded floats per (b,h) row in q/v tile
#define QS_JJ     (32*QS_STRIDE) // 1152 floats per jj row
#define AS_TI     (TJ*32+4)      // 260 floats per ti row in a tile

// Scratch for raw scores between pass 1 and pass 2 (static device global —
// allocation-free per harness rules). 128 MB.
__device__ float g_scratch[(size_t)NBLOCKS * NT * NTHREADS * TJ];

typedef unsigned long long ull;

__device__ __forceinline__ float2 f2mul(float2 a, float2 b) {
    ull ra = *(ull*)&a, rb = *(ull*)&b, rd;
    asm("mul.rn.f32x2 %0, %1, %2;" : "=l"(rd) : "l"(ra), "l"(rb));
    return *(float2*)&rd;
}
__device__ __forceinline__ float2 f2fma(float2 a, float2 b, float2 c) {
    ull ra = *(ull*)&a, rb = *(ull*)&b, rc = *(ull*)&c, rd;
    asm("fma.rn.f32x2 %0, %1, %2, %3;" : "=l"(rd) : "l"(ra), "l"(rb), "l"(rc));
    return *(float2*)&rd;
}

__global__ __launch_bounds__(NTHREADS, 1)
void rel_attn_kernel(const float* __restrict__ q,
                     const float* __restrict__ k,
                     const float* __restrict__ v,
                     const float* __restrict__ ak,
                     float* __restrict__ out,
                     float* __restrict__ attn)
{
    __shared__ float q_s[TJ * QS_JJ];   // 9216 floats (36,864 B) — q in pass1, v in pass2
    __shared__ float a_s[TI * AS_TI];   // 2080 floats (8,320 B)

    const int tid  = threadIdx.x;
    const int blk  = blockIdx.x;
    const int warp = tid >> 5;
    const int lane = tid & 31;
    const int ti    = lane >> 2;        // 0..7 : which i-row of this CTA
    const int bhsub = lane & 3;
    const int bh    = warp * 4 + bhsub; // 0..31
    const int b = bh >> 3, h = bh & 7;
    const int i0 = blk * TI;
    const int i  = i0 + ti;

    // k[b, i, h, 0:32] lives in registers as 16 f32x2
    float2 kr[16];
    {
        const float4* kp = (const float4*)(k + ((size_t)(b * LSEQ + i)) * 256 + h * 32);
        #pragma unroll
        for (int d4 = 0; d4 < 8; d4++) {
            float4 t = kp[d4];
            kr[d4*2]   = make_float2(t.x, t.y);
            kr[d4*2+1] = make_float2(t.z, t.w);
        }
    }

    const float inv_T = 0.17677669529663687f; // 1/sqrt(32)
    float m = -INFINITY, l = 0.0f;

    // ================= PASS 1: scores + online (m, l) =================
    for (int jt = 0; jt < NT; jt++) {
        const int j0 = jt * TJ;
        __syncthreads(); // previous tile's smem reads complete before restage

        // Stage q tile: TJ x 4b x 256 floats = 2048 float4, 8 per thread (coalesced)
        {
            const float4* qg = (const float4*)q;
            #pragma unroll
            for (int r = 0; r < 8; r++) {
                int idx = tid + r * NTHREADS;
                int jj = idx >> 8; int rem = idx & 255;
                int bb = rem >> 6; int c4 = rem & 63;      // c4 = h*8 + d4
                float4 val = qg[((size_t)(bb * LSEQ + j0 + jj)) * 64 + c4];
                int hh = c4 >> 3, d4 = c4 & 7;
                *(float4*)&q_s[jj * QS_JJ + (bb * 8 + hh) * QS_STRIDE + d4 * 4] = val;
            }
        }
        // Stage a tile: TI x TJ x 32 floats = 512 float4, 2 per thread
        {
            const float4* ag = (const float4*)ak;
            #pragma unroll
            for (int r = 0; r < 2; r++) {
                int idx = tid + r * NTHREADS;
                int tii = idx >> 6; int jj = (idx >> 3) & 7; int d4 = idx & 7;
                float4 val = ag[((size_t)((i0 + tii) * LSEQ + j0 + jj)) * 8 + d4];
                *(float4*)&a_s[tii * AS_TI + jj * 32 + d4 * 4] = val;
            }
        }
        __syncthreads();

        float s_buf[TJ];
        #pragma unroll
        for (int jj = 0; jj < TJ; jj++) {
            float2 acc0 = make_float2(0.f, 0.f), acc1 = make_float2(0.f, 0.f);
            #pragma unroll
            for (int d4 = 0; d4 < 8; d4++) {
                float4 A = *(const float4*)&a_s[ti * AS_TI + jj * 32 + d4 * 4];
                float4 Q = *(const float4*)&q_s[jj * QS_JJ + bh * QS_STRIDE + d4 * 4];
                float2 t0 = f2mul(make_float2(A.x, A.y), make_float2(Q.x, Q.y));
                float2 t1 = f2mul(make_float2(A.z, A.w), make_float2(Q.z, Q.w));
                acc0 = f2fma(t0, kr[d4*2],   acc0);
                acc1 = f2fma(t1, kr[d4*2+1], acc1);
            }
            float s = (acc0.x + acc0.y + acc1.x + acc1.y) * inv_T;
            float mn = fmaxf(m, s);
            l = l * __expf(m - mn) + __expf(s - mn);
            m = mn;
            s_buf[jj] = s;
        }

        // raw scores -> scratch, lane-linear layout (fully coalesced 128B/warp)
        float* sp = &g_scratch[(((size_t)blk * NT + jt) * NTHREADS + tid) * TJ];
        *(float4*)sp       = make_float4(s_buf[0], s_buf[1], s_buf[2], s_buf[3]);
        *(float4*)(sp + 4) = make_float4(s_buf[4], s_buf[5], s_buf[6], s_buf[7]);
    }

    const float inv_l = 1.0f / l;

    // ================= PASS 2: p = exp(s-m)/l, attn write, out accum =================
    float2 acc[16];
    #pragma unroll
    for (int r = 0; r < 16; r++) acc[r] = make_float2(0.f, 0.f);

    for (int jt = 0; jt < NT; jt++) {
        const int j0 = jt * TJ;
        __syncthreads(); // previous tile reads (and pass1 final reads) done

        // Stage v tile into q_s (same layout as q)
        {
            const float4* vg = (const float4*)v;
            #pragma unroll
            for (int r = 0; r < 8; r++) {
                int idx = tid + r * NTHREADS;
                int jj = idx >> 8; int rem = idx & 255;
                int bb = rem >> 6; int c4 = rem & 63;
                float4 val = vg[((size_t)(bb * LSEQ + j0 + jj)) * 64 + c4];
                int hh = c4 >> 3, d4 = c4 & 7;
                *(float4*)&q_s[jj * QS_JJ + (bb * 8 + hh) * QS_STRIDE + d4 * 4] = val;
            }
        }
        __syncthreads();

        const float* sp = &g_scratch[(((size_t)blk * NT + jt) * NTHREADS + tid) * TJ];
        float4 sa = *(const float4*)sp;
        float4 sb = *(const float4*)(sp + 4);
        float sv[TJ] = {sa.x, sa.y, sa.z, sa.w, sb.x, sb.y, sb.z, sb.w};
        float pv[TJ];

        #pragma unroll
        for (int jj = 0; jj < TJ; jj++) {
            float p = __expf(sv[jj] - m) * inv_l;
            pv[jj] = p;
            float2 p2 = make_float2(p, p);
            #pragma unroll
            for (int d4 = 0; d4 < 8; d4++) {
                float4 V = *(const float4*)&q_s[jj * QS_JJ + bh * QS_STRIDE + d4 * 4];
                acc[d4*2]   = f2fma(p2, make_float2(V.x, V.y), acc[d4*2]);
                acc[d4*2+1] = f2fma(p2, make_float2(V.z, V.w), acc[d4*2+1]);
            }
        }

        if (attn) {
            float* ap = attn + ((size_t)(bh * LSEQ + i)) * LSEQ + j0;
            *(float4*)ap       = make_float4(pv[0], pv[1], pv[2], pv[3]);
            *(float4*)(ap + 4) = make_float4(pv[4], pv[5], pv[6], pv[7]);
        }
    }

    if (out) {
        float* op = out + ((size_t)(bh * LSEQ + i)) * 32;
        #pragma unroll
        for (int d4 = 0; d4 < 8; d4++) {
            *(float4*)&op[d4 * 4] = make_float4(acc[d4*2].x, acc[d4*2].y,
                                                acc[d4*2+1].x, acc[d4*2+1].y);
        }
    }
}

extern "C" void kernel_launch(void* const* d_in, const int* in_sizes, int n_in,
                              void* d_out, int out_size)
{
    // Identify inputs by size: q/k/v are 1,048,576 floats (in that order),
    // a_k is 33,554,432 floats; int scalars (d_k, d_v, n_head) are ignored.
    const float *q = 0, *k = 0, *v = 0, *ak = 0;
    int qc = 0;
    for (int idx = 0; idx < n_in; idx++) {
        if (in_sizes[idx] == 33554432) {
            ak = (const float*)d_in[idx];
        } else if (in_sizes[idx] == 1048576) {
            if (qc == 0) q = (const float*)d_in[idx];
            else if (qc == 1) k = (const float*)d_in[idx];
            else if (qc == 2) v = (const float*)d_in[idx];
            qc++;
        }
    }

    const long long OUT_N  = 1048576LL;   // B*H*L*DV
    const long long ATTN_N = 33554432LL;  // B*H*L*L
    float* outp  = 0;
    float* attnp = 0;
    long long os = (long long)out_size;
    if (os >= OUT_N + ATTN_N) {           // tuple (out, attn) concatenated
        outp  = (float*)d_out;
        attnp = (float*)d_out + OUT_N;
    } else if (os == ATTN_N) {            // attn only
        attnp = (float*)d_out;
    } else {                              // out only (or unknown -> write out)
        outp = (float*)d_out;
    }

    rel_attn_kernel<<<NBLOCKS, NTHREADS>>>(q, k, v, ak, outp, attnp);
}